// round 1
// baseline (speedup 1.0000x reference)
#include <cuda_runtime.h>

// Problem constants
#define B_   1024
#define T_   512
#define I_   16
#define H_   50
#define G_   200     // 4*H
#define FCD  64
#define NB   4       // batch rows per block
#define NTH  224     // 7 warps; threads 0..199 are gate threads

// Layer-1 hidden sequence scratch: [B][T][H] floats = 104.9 MB (static device global)
__device__ float g_h1[B_ * T_ * H_];

// ---- f32x2 packed helpers (sm_103a FFMA2) ----
__device__ __forceinline__ void fma2(unsigned long long& acc,
                                     unsigned long long a,
                                     unsigned long long b) {
    asm("fma.rn.f32x2 %0, %1, %2, %0;" : "+l"(acc) : "l"(a), "l"(b));
}
__device__ __forceinline__ unsigned long long pk2(float x, float y) {
    unsigned long long r;
    asm("mov.b64 %0, {%1, %2};" : "=l"(r) : "f"(x), "f"(y));
    return r;
}
__device__ __forceinline__ float2 unpk(unsigned long long v) {
    float2 r;
    asm("mov.b64 {%0, %1}, %2;" : "=f"(r.x), "=f"(r.y) : "l"(v));
    return r;
}

__device__ __forceinline__ float sigf(float x) {
    return 1.0f / (1.0f + __expf(-x));
}
__device__ __forceinline__ float tanh_f(float x) {
    return 2.0f / (1.0f + __expf(-2.0f * x)) - 1.0f;
}

// One LSTM layer, persistent per-block over all T timesteps.
// IN  = logical input width (16 for layer 1, 50 for layer 2)
// INP = padded input width, multiple of 4 (16 / 52)
// FINAL: layer 2 — reads g_h1 as input, runs FC head at the end.
//        !FINAL: layer 1 — reads x (param `in`), writes g_h1.
template <int IN, int INP, bool FINAL>
__global__ __launch_bounds__(NTH, 2)
void lstm_kernel(const float* __restrict__ in,
                 const float* __restrict__ w_ih,   // [G, IN]
                 const float* __restrict__ w_hh,   // [G, H]
                 const float* __restrict__ b_ih,   // [G]
                 const float* __restrict__ b_hh,   // [G]
                 const float* __restrict__ fc1_w,  // [FCD, H]
                 const float* __restrict__ fc1_b,  // [FCD]
                 const float* __restrict__ fc2_w,  // [1, FCD]
                 const float* __restrict__ fc2_b,  // [1]
                 float* __restrict__ out)          // [B, 1]
{
    __shared__ __align__(16) float h_sh[NB][52];        // hidden state (padded to 52)
    __shared__ __align__(16) float in_sh[2][NB][INP];   // double-buffered input tile
    __shared__ float gate_sh[NB][G_];
    __shared__ float fcsh[FCD];

    const int tid  = threadIdx.x;
    const int row0 = blockIdx.x * NB;

    const float* input = FINAL ? (const float*)g_h1 : in;
    const int in_row_stride = T_ * IN;

    // ---- zero shared state (incl. pads: garbage*0 could be NaN) ----
    for (int i = tid; i < NB * 52; i += NTH) ((float*)h_sh)[i] = 0.0f;
    for (int i = tid; i < 2 * NB * INP; i += NTH) ((float*)in_sh)[i] = 0.0f;
    __syncthreads();

    // ---- load this gate's weight rows into registers, packed as f32x2 pairs ----
    const int g = tid;
    unsigned long long wih2[INP / 2];
    unsigned long long whh2[26];   // 52/2
    float bias = 0.0f;
    if (g < G_) {
        #pragma unroll
        for (int k2 = 0; k2 < INP / 2; k2++) {
            float a = (2 * k2     < IN) ? __ldg(&w_ih[g * IN + 2 * k2])     : 0.0f;
            float b = (2 * k2 + 1 < IN) ? __ldg(&w_ih[g * IN + 2 * k2 + 1]) : 0.0f;
            wih2[k2] = pk2(a, b);
        }
        #pragma unroll
        for (int k2 = 0; k2 < 26; k2++) {
            float a = (2 * k2     < H_) ? __ldg(&w_hh[g * H_ + 2 * k2])     : 0.0f;
            float b = (2 * k2 + 1 < H_) ? __ldg(&w_hh[g * H_ + 2 * k2 + 1]) : 0.0f;
            whh2[k2] = pk2(a, b);
        }
        bias = __ldg(&b_ih[g]) + __ldg(&b_hh[g]);
    }

    // cell state: thread tid<200 owns (row rc, hidden unit jc)
    const int rc = tid / H_;
    const int jc = tid - rc * H_;
    float c_state = 0.0f;

    // ---- preload t = 0 input tile ----
    if (tid < NB * IN) {
        int r = tid / IN, k = tid - r * IN;
        in_sh[0][r][k] = input[(row0 + r) * in_row_stride + k];
    }
    __syncthreads();

    int buf = 0;
    for (int t = 0; t < T_; t++) {
        // prefetch next timestep's input (overlaps gate compute)
        float pref = 0.0f;
        int pr = 0, pkk = 0;
        if (t + 1 < T_ && tid < NB * IN) {
            pr = tid / IN; pkk = tid - pr * IN;
            pref = input[(row0 + pr) * in_row_stride + (t + 1) * IN + pkk];
        }

        // ---- gate phase: acc[r] = bias + x_t . w_ih[g] + h . w_hh[g] ----
        if (g < G_) {
            unsigned long long acc[NB];
            #pragma unroll
            for (int r = 0; r < NB; r++) acc[r] = pk2(bias, 0.0f);

            #pragma unroll
            for (int q = 0; q < INP / 4; q++) {
                #pragma unroll
                for (int r = 0; r < NB; r++) {
                    const ulonglong2 v =
                        *(const ulonglong2*)&in_sh[buf][r][4 * q];
                    fma2(acc[r], wih2[2 * q],     v.x);
                    fma2(acc[r], wih2[2 * q + 1], v.y);
                }
            }
            #pragma unroll
            for (int q = 0; q < 13; q++) {   // 52/4
                #pragma unroll
                for (int r = 0; r < NB; r++) {
                    const ulonglong2 v =
                        *(const ulonglong2*)&h_sh[r][4 * q];
                    fma2(acc[r], whh2[2 * q],     v.x);
                    fma2(acc[r], whh2[2 * q + 1], v.y);
                }
            }
            #pragma unroll
            for (int r = 0; r < NB; r++) {
                float2 s = unpk(acc[r]);
                gate_sh[r][g] = s.x + s.y;
            }
        }
        __syncthreads();

        // ---- combine phase: LSTM cell update (gate order: i, f, g, o) ----
        if (tid < G_) {
            float ig = sigf(gate_sh[rc][jc]);
            float fg = sigf(gate_sh[rc][H_ + jc]);
            float gg = tanh_f(gate_sh[rc][2 * H_ + jc]);
            float og = sigf(gate_sh[rc][3 * H_ + jc]);
            c_state = fg * c_state + ig * gg;
            float h = og * tanh_f(c_state);
            h_sh[rc][jc] = h;
            if (!FINAL) {
                g_h1[(row0 + rc) * (T_ * H_) + t * H_ + jc] = h;
            }
        }
        // commit prefetched input into the other buffer
        if (t + 1 < T_ && tid < NB * IN) {
            in_sh[buf ^ 1][pr][pkk] = pref;
        }
        __syncthreads();
        buf ^= 1;
    }

    // ---- FC head (layer-2 kernel only): out = relu(h2 @ fc1^T + b1) @ fc2^T + b2 ----
    if (FINAL) {
        for (int r = 0; r < NB; r++) {
            if (tid < FCD) {
                float a = __ldg(&fc1_b[tid]);
                #pragma unroll
                for (int k = 0; k < H_; k++)
                    a += __ldg(&fc1_w[tid * H_ + k]) * h_sh[r][k];
                a = fmaxf(a, 0.0f);
                fcsh[tid] = a * __ldg(&fc2_w[tid]);
            }
            __syncthreads();
            if (tid == 0) {
                float s = __ldg(&fc2_b[0]);
                #pragma unroll
                for (int k = 0; k < FCD; k++) s += fcsh[k];
                out[row0 + r] = s;
            }
            __syncthreads();
        }
    }
}

extern "C" void kernel_launch(void* const* d_in, const int* in_sizes, int n_in,
                              void* d_out, int out_size) {
    const float* x     = (const float*)d_in[0];
    const float* w_ih0 = (const float*)d_in[1];
    const float* w_hh0 = (const float*)d_in[2];
    const float* b_ih0 = (const float*)d_in[3];
    const float* b_hh0 = (const float*)d_in[4];
    const float* w_ih1 = (const float*)d_in[5];
    const float* w_hh1 = (const float*)d_in[6];
    const float* b_ih1 = (const float*)d_in[7];
    const float* b_hh1 = (const float*)d_in[8];
    const float* fc1_w = (const float*)d_in[9];
    const float* fc1_b = (const float*)d_in[10];
    const float* fc2_w = (const float*)d_in[11];
    const float* fc2_b = (const float*)d_in[12];
    float* out = (float*)d_out;

    // Layer 1: reads x, writes g_h1
    lstm_kernel<I_, 16, false><<<B_ / NB, NTH>>>(
        x, w_ih0, w_hh0, b_ih0, b_hh0,
        nullptr, nullptr, nullptr, nullptr, nullptr);

    // Layer 2 + FC head: reads g_h1, writes out
    lstm_kernel<H_, 52, true><<<B_ / NB, NTH>>>(
        nullptr, w_ih1, w_hh1, b_ih1, b_hh1,
        fc1_w, fc1_b, fc2_w, fc2_b, out);
}